// round 16
// baseline (speedup 1.0000x reference)
#include <cuda_runtime.h>
#include <math.h>
#include <stdint.h>

#define NN   2048
#define KK   16384      // NN * 8
#define TAU  10
#define NB   8

// dense trace vector for layer 0
__device__ __align__(16) float g_x0[KK];
// spike bitmasks: g_bits[0] = layer-0 spikes, g_bits[1] = layer-1 spikes
__device__ unsigned int g_bits[2][NN / 32];

// ---------------- Threefry-2x32 (JAX-compatible, 20 rounds) ----------------
__host__ __device__ inline uint32_t tf_rotl(uint32_t v, int r) {
    return (v << r) | (v >> (32 - r));
}

__host__ __device__ inline void tf_block(uint32_t k0, uint32_t k1,
                                         uint32_t c0, uint32_t c1,
                                         uint32_t& o0, uint32_t& o1) {
    uint32_t ks2 = k0 ^ k1 ^ 0x1BD11BDAu;
    uint32_t x0 = c0 + k0, x1 = c1 + k1;
#define TF_RND(r) { x0 += x1; x1 = tf_rotl(x1, (r)); x1 ^= x0; }
    TF_RND(13) TF_RND(15) TF_RND(26) TF_RND(6)
    x0 += k1;  x1 += ks2 + 1u;
    TF_RND(17) TF_RND(29) TF_RND(16) TF_RND(24)
    x0 += ks2; x1 += k0 + 2u;
    TF_RND(13) TF_RND(15) TF_RND(26) TF_RND(6)
    x0 += k0;  x1 += k1 + 3u;
    TF_RND(17) TF_RND(29) TF_RND(16) TF_RND(24)
    x0 += k1;  x1 += ks2 + 4u;
    TF_RND(13) TF_RND(15) TF_RND(26) TF_RND(6)
    x0 += ks2; x1 += k0 + 5u;
#undef TF_RND
    o0 = x0; o1 = x1;
}

__device__ inline float tf_uniform(uint32_t k0, uint32_t k1, uint32_t e) {
    uint32_t b1, b2;
    tf_block(k0, k1, 0u, e, b1, b2);
    uint32_t bits = b1 ^ b2;
    return __uint_as_float((bits >> 9) | 0x3f800000u) - 1.0f;
}

// ---------------- Kernel 1: layer-0 input trace (+ zero the bitmasks) -----
__global__ void trace_kernel(const float* __restrict__ inp) {
    __shared__ float filt[TAU * NB];
    int tid = threadIdx.x;
    if (blockIdx.x == 0 && tid < 2 * (NN / 32)) {
        ((unsigned int*)g_bits)[tid] = 0u;
    }
    if (tid < TAU * NB) {
        int t = tid / NB, b = tid % NB;
        const float mupi = 1.5707963267948966f;
        const float pif  = 3.14159265358979f;
        float arg = mupi * log1pf((float)t) - mupi * (float)b;
        arg = fminf(fmaxf(arg, -pif), pif);
        filt[tid] = 0.5f * (1.0f + cosf(arg));
    }
    __syncthreads();
    int i = blockIdx.x * blockDim.x + tid;
    if (i < NN) {
        float acc[NB];
#pragma unroll
        for (int b = 0; b < NB; b++) acc[b] = 0.0f;
#pragma unroll
        for (int t = 0; t < TAU; t++) {
            float v = inp[i * TAU + (TAU - 1 - t)];
#pragma unroll
            for (int b = 0; b < NB; b++) acc[b] += v * filt[t * NB + b];
        }
#pragma unroll
        for (int b = 0; b < NB; b++) g_x0[i * NB + b] = acc[b];
    }
}

// prefetch this block's full 64KB W row into L2 (512 x 128B lines; data is
// independent of the upstream kernel, so it may run BEFORE the PDL sync)
__device__ __forceinline__ void prefetch_row_l2(const float* W, int row) {
    const char* wrow = reinterpret_cast<const char*>(W + (size_t)row * KK);
#pragma unroll
    for (int q = 0; q < 2; q++) {
        const char* p = wrow + ((size_t)threadIdx.x + q * 256) * 128;
        asm volatile("prefetch.global.L2 [%0];" :: "l"(p));
    }
}

// block-wide reduce over 256 threads (8 warps); result valid in thread 0
__device__ inline float block_reduce_256(float acc, float* warpsum) {
#pragma unroll
    for (int off = 16; off > 0; off >>= 1)
        acc += __shfl_down_sync(0xffffffffu, acc, off);
    int lane = threadIdx.x & 31, wid = threadIdx.x >> 5;
    if (lane == 0) warpsum[wid] = acc;
    __syncthreads();
    float tot = 0.0f;
    if (threadIdx.x == 0) {
#pragma unroll
        for (int w = 0; w < 8; w++) tot += warpsum[w];
    }
    return tot;
}

// ---------------- Kernel 2: layer 0, dense matvec (R8 body + PDL prologue) -
__global__ __launch_bounds__(256) void layer0_kernel(
    const float* __restrict__ W, const float* __restrict__ bias,
    float* __restrict__ p_out, float* __restrict__ s_out,
    uint32_t key0, uint32_t key1)
{
    __shared__ float warpsum[8];
    const int row = blockIdx.x;

    prefetch_row_l2(W, row);            // overlap with trace_kernel drain
    cudaGridDependencySynchronize();    // g_x0 ready after this

    const float4* w4 = reinterpret_cast<const float4*>(W + (size_t)row * KK);
    const float4* x4 = reinterpret_cast<const float4*>(g_x0);

    float acc = 0.0f;
#pragma unroll
    for (int it = 0; it < 16; it++) {
        int j = it * 256 + threadIdx.x;
        float4 w = w4[j];
        float4 xv = x4[j];
        acc += w.x * xv.x + w.y * xv.y + w.z * xv.z + w.w * xv.w;
    }

    float tot = block_reduce_256(acc, warpsum);
    if (threadIdx.x == 0) {
        float z = tot + bias[row];
        float p = 1.0f / (1.0f + expf(-z));
        float u = tf_uniform(key0, key1, (uint32_t)row);
        float s = (u < p) ? 1.0f : 0.0f;
        p_out[row] = p;
        s_out[row] = s;
        if (s > 0.0f)
            atomicOr(&g_bits[0][row >> 5], 1u << (row & 31));
    }
}

// ---------------- Kernel 3: layers 1/2 — pair-granular gather (R8 body) ---
__global__ __launch_bounds__(256) void layer_pair(
    const float* __restrict__ W, const float* __restrict__ bias,
    int mask_in, int mask_out,
    float* __restrict__ p_out, float* __restrict__ s_out,
    uint32_t key0, uint32_t key1, float f1)
{
    __shared__ unsigned int sm_bits[NN / 32];
    __shared__ unsigned short sm_pairs[NN / 2];
    __shared__ int sm_warp[8];
    __shared__ int sm_cnt;
    __shared__ float warpsum[8];

    const int t = threadIdx.x;
    const int row = blockIdx.x;

    prefetch_row_l2(W, row);            // overlap with upstream drain
    cudaGridDependencySynchronize();    // g_bits[mask_in] ready after this

    if (t < NN / 32) sm_bits[t] = g_bits[mask_in][t];
    __syncthreads();

    // ---- build active-pair list (deterministic, ascending) ----
    const unsigned int word = sm_bits[t >> 2];
    unsigned int f[4];
    int c = 0;
#pragma unroll
    for (int q = 0; q < 4; q++) {
        f[q] = (word >> ((t & 3) * 8 + 2 * q)) & 3u;
        c += (f[q] != 0u);
    }
    int lane = t & 31, wid = t >> 5;
    int incl = c;
#pragma unroll
    for (int off = 1; off < 32; off <<= 1) {
        int v = __shfl_up_sync(0xffffffffu, incl, off);
        if (lane >= off) incl += v;
    }
    if (lane == 31) sm_warp[wid] = incl;
    __syncthreads();
    if (t == 0) {
        int run = 0;
#pragma unroll
        for (int w = 0; w < 8; w++) { int v = sm_warp[w]; sm_warp[w] = run; run += v; }
        sm_cnt = run;
    }
    __syncthreads();
    int o = sm_warp[wid] + (incl - c);
#pragma unroll
    for (int q = 0; q < 4; q++) {
        if (f[q] != 0u) sm_pairs[o++] = (unsigned short)(4 * t + q);
    }
    __syncthreads();

    const int cnt = sm_cnt;
    const float2* __restrict__ w2 =
        reinterpret_cast<const float2*>(W + (size_t)row * KK);

    float2 A[4], B[4];
#pragma unroll
    for (int q = 0; q < 4; q++) {
        int k = t + q * 256;
        bool v = (k < cnt);
        int p = v ? (int)sm_pairs[k] : 0;
        unsigned int bb = v ? ((sm_bits[p >> 4] >> ((p & 15) * 2)) & 3u) : 0u;
        A[q] = (bb & 1u) ? w2[(size_t)p * 8]     : make_float2(0.0f, 0.0f);
        B[q] = (bb & 2u) ? w2[(size_t)p * 8 + 4] : make_float2(0.0f, 0.0f);
    }
    float acc = 0.0f;
#pragma unroll
    for (int q = 0; q < 4; q++) {
        acc += (A[q].x + f1 * A[q].y) + (B[q].x + f1 * B[q].y);
    }

    float tot = block_reduce_256(acc, warpsum);
    if (threadIdx.x == 0) {
        float z = tot + bias[row];
        float p = 1.0f / (1.0f + expf(-z));
        float u = tf_uniform(key0, key1, (uint32_t)row);
        float s = (u < p) ? 1.0f : 0.0f;
        p_out[row] = p;
        s_out[row] = s;
        if (mask_out >= 0 && s > 0.0f)
            atomicOr(&g_bits[mask_out][row >> 5], 1u << (row & 31));
    }
}

extern "C" void kernel_launch(void* const* d_in, const int* in_sizes, int n_in,
                              void* d_out, int out_size) {
    const float* inp  = (const float*)d_in[0];
    const float* ffw0 = (const float*)d_in[1];
    const float* b0   = (const float*)d_in[3];
    const float* ffw1 = (const float*)d_in[4];
    const float* b1   = (const float*)d_in[6];
    const float* ffw2 = (const float*)d_in[7];
    const float* b2   = (const float*)d_in[9];
    float* out = (float*)d_out;

    uint32_t k0a, k0b, k1a, k1b, k2a, k2b;
    tf_block(0u, 42u, 0u, 0u, k0a, k0b);
    tf_block(0u, 42u, 0u, 1u, k1a, k1b);
    tf_block(0u, 42u, 0u, 2u, k2a, k2b);

    const float mupi = 1.5707963267948966f;
    const float pif  = 3.14159265358979f;
    float f1 = 0.5f * (1.0f + cosf(fminf(fmaxf(-mupi, -pif), pif)));  // ~0.5

    float* p2 = out;
    float* s2 = out + 2048;
    float* p0 = out + 4096;
    float* p1 = out + 6144;
    float* s0 = out + 8192;
    float* s1 = out + 10240;

    trace_kernel<<<16, 128>>>(inp);

    // PDL launches: next grid may begin (and prefetch W into L2) while the
    // previous grid drains; cudaGridDependencySynchronize() in the kernel
    // guards all upstream-dependent reads.
    cudaLaunchAttribute attr[1];
    attr[0].id = cudaLaunchAttributeProgrammaticStreamSerialization;
    attr[0].val.programmaticStreamSerializationAllowed = 1;

    cudaLaunchConfig_t cfg = {};
    cfg.gridDim = dim3(NN);
    cfg.blockDim = dim3(256);
    cfg.dynamicSmemBytes = 0;
    cfg.stream = 0;              // legacy default stream (same as <<<>>>)
    cfg.attrs = attr;
    cfg.numAttrs = 1;

    cudaLaunchKernelEx(&cfg, layer0_kernel, ffw0, b0, p0, s0, k0a, k0b);
    cudaLaunchKernelEx(&cfg, layer_pair, ffw1, b1, 0,  1, p1, s1, k1a, k1b, f1);
    cudaLaunchKernelEx(&cfg, layer_pair, ffw2, b2, 1, -1, p2, s2, k2a, k2b, f1);
}

// round 17
// speedup vs baseline: 1.0634x; 1.0634x over previous
#include <cuda_runtime.h>
#include <math.h>
#include <stdint.h>

#define NN   2048
#define KK   16384      // NN * 8
#define TAU  10
#define NB   8

// dense trace vector for layer 0
__device__ __align__(16) float g_x0[KK];
// spike bitmasks: g_bits[0] = layer-0 spikes, g_bits[1] = layer-1 spikes
__device__ unsigned int g_bits[2][NN / 32];

// ---------------- Threefry-2x32 (JAX-compatible, 20 rounds) ----------------
__host__ __device__ inline uint32_t tf_rotl(uint32_t v, int r) {
    return (v << r) | (v >> (32 - r));
}

__host__ __device__ inline void tf_block(uint32_t k0, uint32_t k1,
                                         uint32_t c0, uint32_t c1,
                                         uint32_t& o0, uint32_t& o1) {
    uint32_t ks2 = k0 ^ k1 ^ 0x1BD11BDAu;
    uint32_t x0 = c0 + k0, x1 = c1 + k1;
#define TF_RND(r) { x0 += x1; x1 = tf_rotl(x1, (r)); x1 ^= x0; }
    TF_RND(13) TF_RND(15) TF_RND(26) TF_RND(6)
    x0 += k1;  x1 += ks2 + 1u;
    TF_RND(17) TF_RND(29) TF_RND(16) TF_RND(24)
    x0 += ks2; x1 += k0 + 2u;
    TF_RND(13) TF_RND(15) TF_RND(26) TF_RND(6)
    x0 += k0;  x1 += k1 + 3u;
    TF_RND(17) TF_RND(29) TF_RND(16) TF_RND(24)
    x0 += k1;  x1 += ks2 + 4u;
    TF_RND(13) TF_RND(15) TF_RND(26) TF_RND(6)
    x0 += ks2; x1 += k0 + 5u;
#undef TF_RND
    o0 = x0; o1 = x1;
}

__device__ inline float tf_uniform(uint32_t k0, uint32_t k1, uint32_t e) {
    uint32_t b1, b2;
    tf_block(k0, k1, 0u, e, b1, b2);
    uint32_t bits = b1 ^ b2;
    return __uint_as_float((bits >> 9) | 0x3f800000u) - 1.0f;
}

// ---------------- Kernel 1: layer-0 input trace (+ zero the bitmasks) -----
__global__ void trace_kernel(const float* __restrict__ inp) {
    __shared__ float filt[TAU * NB];
    int tid = threadIdx.x;
    if (blockIdx.x == 0 && tid < 2 * (NN / 32)) {
        ((unsigned int*)g_bits)[tid] = 0u;
    }
    if (tid < TAU * NB) {
        int t = tid / NB, b = tid % NB;
        const float mupi = 1.5707963267948966f;
        const float pif  = 3.14159265358979f;
        float arg = mupi * log1pf((float)t) - mupi * (float)b;
        arg = fminf(fmaxf(arg, -pif), pif);
        filt[tid] = 0.5f * (1.0f + cosf(arg));
    }
    __syncthreads();
    int i = blockIdx.x * blockDim.x + tid;
    if (i < NN) {
        float acc[NB];
#pragma unroll
        for (int b = 0; b < NB; b++) acc[b] = 0.0f;
#pragma unroll
        for (int t = 0; t < TAU; t++) {
            float v = inp[i * TAU + (TAU - 1 - t)];
#pragma unroll
            for (int b = 0; b < NB; b++) acc[b] += v * filt[t * NB + b];
        }
#pragma unroll
        for (int b = 0; b < NB; b++) g_x0[i * NB + b] = acc[b];
    }
}

// block-wide reduce over 256 threads (8 warps); result valid in thread 0
__device__ inline float block_reduce_256(float acc, float* warpsum) {
#pragma unroll
    for (int off = 16; off > 0; off >>= 1)
        acc += __shfl_down_sync(0xffffffffu, acc, off);
    int lane = threadIdx.x & 31, wid = threadIdx.x >> 5;
    if (lane == 0) warpsum[wid] = acc;
    __syncthreads();
    float tot = 0.0f;
    if (threadIdx.x == 0) {
#pragma unroll
        for (int w = 0; w < 8; w++) tot += warpsum[w];
    }
    return tot;
}

// ---------------- Kernel 2: layer 0, dense matvec (R8 exact) --------------
__global__ __launch_bounds__(256) void layer0_kernel(
    const float* __restrict__ W, const float* __restrict__ bias,
    float* __restrict__ p_out, float* __restrict__ s_out,
    uint32_t key0, uint32_t key1)
{
    __shared__ float warpsum[8];
    const int row = blockIdx.x;
    const float4* w4 = reinterpret_cast<const float4*>(W + (size_t)row * KK);
    const float4* x4 = reinterpret_cast<const float4*>(g_x0);

    float acc = 0.0f;
#pragma unroll
    for (int it = 0; it < 16; it++) {
        int j = it * 256 + threadIdx.x;
        float4 w = w4[j];
        float4 xv = x4[j];
        acc += w.x * xv.x + w.y * xv.y + w.z * xv.z + w.w * xv.w;
    }

    float tot = block_reduce_256(acc, warpsum);
    if (threadIdx.x == 0) {
        float z = tot + bias[row];
        float p = 1.0f / (1.0f + expf(-z));
        float u = tf_uniform(key0, key1, (uint32_t)row);
        float s = (u < p) ? 1.0f : 0.0f;
        p_out[row] = p;
        s_out[row] = s;
        if (s > 0.0f)
            atomicOr(&g_bits[0][row >> 5], 1u << (row & 31));
    }
}

// ---------------- Kernel 3: layers 1/2 — pair gather, 128thr x 8 slots ----
// Same math as R8 (deterministic ascending pair list, predicated member
// loads contributing exact zeros), but 128 threads x 8 pair-slots/thread:
// 16 outstanding loads per thread (vs 8) to raise the DRAM fill rate, which
// is what binds this kernel (65% of spec vs 73% for the dense pattern).
__global__ __launch_bounds__(128) void layer_pair(
    const float* __restrict__ W, const float* __restrict__ bias,
    int mask_in, int mask_out,
    float* __restrict__ p_out, float* __restrict__ s_out,
    uint32_t key0, uint32_t key1, float f1)
{
    __shared__ unsigned int sm_bits[NN / 32];          // 64 words
    __shared__ unsigned short sm_pairs[NN / 2];        // ascending active pairs
    __shared__ int sm_warp[4];
    __shared__ int sm_cnt;
    __shared__ float warpsum[4];

    const int t = threadIdx.x;                         // 0..127
    if (t < NN / 32) sm_bits[t] = g_bits[mask_in][t];
    __syncthreads();

    // ---- build active-pair list (deterministic, ascending) ----
    // thread t owns pairs 8t..8t+7; pair p's 2 bits sit in sm_bits[p>>4]
    // at position (p&15)*2; for p = 8t+q that's word t>>1, pos ((t&1)*8+q)*2.
    const unsigned int word = sm_bits[t >> 1];
    const int basebit = (t & 1) * 16;
    unsigned int f[8];
    int c = 0;
#pragma unroll
    for (int q = 0; q < 8; q++) {
        f[q] = (word >> (basebit + 2 * q)) & 3u;       // bits of (2p, 2p+1)
        c += (f[q] != 0u);
    }
    int lane = t & 31, wid = t >> 5;
    int incl = c;
#pragma unroll
    for (int off = 1; off < 32; off <<= 1) {
        int v = __shfl_up_sync(0xffffffffu, incl, off);
        if (lane >= off) incl += v;
    }
    if (lane == 31) sm_warp[wid] = incl;
    __syncthreads();
    if (t == 0) {
        int run = 0;
#pragma unroll
        for (int w = 0; w < 4; w++) { int v = sm_warp[w]; sm_warp[w] = run; run += v; }
        sm_cnt = run;
    }
    __syncthreads();
    int o = sm_warp[wid] + (incl - c);
#pragma unroll
    for (int q = 0; q < 8; q++) {
        if (f[q] != 0u) sm_pairs[o++] = (unsigned short)(8 * t + q);
    }
    __syncthreads();

    const int cnt = sm_cnt;
    const int row = blockIdx.x;
    const float2* __restrict__ w2 =
        reinterpret_cast<const float2*>(W + (size_t)row * KK);

    // ---- gather: up to 8 pairs/thread, 16 predicated loads in flight ----
    float2 A[8], B[8];
#pragma unroll
    for (int q = 0; q < 8; q++) {
        int k = t + q * 128;
        bool v = (k < cnt);
        int p = v ? (int)sm_pairs[k] : 0;
        unsigned int bb = v ? ((sm_bits[p >> 4] >> ((p & 15) * 2)) & 3u) : 0u;
        A[q] = (bb & 1u) ? w2[(size_t)p * 8]     : make_float2(0.0f, 0.0f);
        B[q] = (bb & 2u) ? w2[(size_t)p * 8 + 4] : make_float2(0.0f, 0.0f);
    }
    float acc = 0.0f;
#pragma unroll
    for (int q = 0; q < 8; q++) {
        acc += (A[q].x + f1 * A[q].y) + (B[q].x + f1 * B[q].y);
    }

    // block reduce over 4 warps
#pragma unroll
    for (int off = 16; off > 0; off >>= 1)
        acc += __shfl_down_sync(0xffffffffu, acc, off);
    if (lane == 0) warpsum[wid] = acc;
    __syncthreads();

    if (t == 0) {
        float tot = 0.0f;
#pragma unroll
        for (int w = 0; w < 4; w++) tot += warpsum[w];
        float z = tot + bias[row];
        float p = 1.0f / (1.0f + expf(-z));
        float u = tf_uniform(key0, key1, (uint32_t)row);
        float s = (u < p) ? 1.0f : 0.0f;
        p_out[row] = p;
        s_out[row] = s;
        if (mask_out >= 0 && s > 0.0f)
            atomicOr(&g_bits[mask_out][row >> 5], 1u << (row & 31));
    }
}

extern "C" void kernel_launch(void* const* d_in, const int* in_sizes, int n_in,
                              void* d_out, int out_size) {
    const float* inp  = (const float*)d_in[0];
    const float* ffw0 = (const float*)d_in[1];
    const float* b0   = (const float*)d_in[3];
    const float* ffw1 = (const float*)d_in[4];
    const float* b1   = (const float*)d_in[6];
    const float* ffw2 = (const float*)d_in[7];
    const float* b2   = (const float*)d_in[9];
    float* out = (float*)d_out;

    // root key = (0, 42); partitionable split: key_i = block(root, (0, i))
    uint32_t k0a, k0b, k1a, k1b, k2a, k2b;
    tf_block(0u, 42u, 0u, 0u, k0a, k0b);
    tf_block(0u, 42u, 0u, 1u, k1a, k1b);
    tf_block(0u, 42u, 0u, 2u, k2a, k2b);

    // FF_FILT[0,1]; entries b>=2 are exactly 0 (clip to -pi), b=0 is exactly 1
    const float mupi = 1.5707963267948966f;
    const float pif  = 3.14159265358979f;
    float f1 = 0.5f * (1.0f + cosf(fminf(fmaxf(-mupi, -pif), pif)));  // ~0.5

    // output layout: [p2 | s2 | p0 | p1 | s0 | s1], 6 * 2048 floats
    float* p2 = out;
    float* s2 = out + 2048;
    float* p0 = out + 4096;
    float* p1 = out + 6144;
    float* s0 = out + 8192;
    float* s1 = out + 10240;

    trace_kernel<<<16, 128>>>(inp);
    layer0_kernel<<<NN, 256>>>(ffw0, b0, p0, s0, k0a, k0b);
    layer_pair<<<NN, 128>>>(ffw1, b1, 0,  1, p1, s1, k1a, k1b, f1);
    layer_pair<<<NN, 128>>>(ffw2, b2, 1, -1, p2, s2, k2a, k2b, f1);
}